// round 4
// baseline (speedup 1.0000x reference)
#include <cuda_runtime.h>

typedef unsigned long long ull;

#define T_OBS 8
#define T_PRE 12
#define BATCH 524288
#define HID 8
#define NTHREADS 128
#define M_ELEMS 2                                   // elements per thread = 1 f32x2 pair
#define NBLOCKS (BATCH / M_ELEMS / NTHREADS)        // 2048

// packed duplicated weights: [phase][unit j][gate g][12] with
// slot 0..1 = wx (combined input weights), 2..9 = whh, 10 = combined bias, 11 = pad
__device__ ull g_wp[2 * 8 * 4 * 12];

__device__ __forceinline__ ull pack2(float lo, float hi) {
    ull r; asm("mov.b64 %0, {%1, %2};" : "=l"(r) : "f"(lo), "f"(hi)); return r;
}
__device__ __forceinline__ void unpack2(ull v, float &lo, float &hi) {
    asm("mov.b64 {%0, %1}, %2;" : "=f"(lo), "=f"(hi) : "l"(v));
}
__device__ __forceinline__ ull fma2(ull a, ull b, ull c) {
    ull d; asm("fma.rn.f32x2 %0, %1, %2, %3;" : "=l"(d) : "l"(a), "l"(b), "l"(c)); return d;
}
// HW tanh: 1 MUFU op, max abs err ~2^-10.7
__device__ __forceinline__ float tanh_hw(float x) {
    float y; asm("tanh.approx.f32 %0, %1;" : "=f"(y) : "f"(x)); return y;
}
// sigmoid(x) = 0.5 + 0.5*tanh(x/2) : MUL, MUFU, FMA
__device__ __forceinline__ float sig_f(float x) {
    return fmaf(tanh_hw(0.5f * x), 0.5f, 0.5f);
}

// ---------------------------------------------------------------------------
// prep: fold embedding into gate matrices; duplicate-pack everything for f32x2
//   W_comb[r][i] = sum_e W_ih[r][e] * W_in[e][i]
//   b_comb[r]    = sum_e W_ih[r][e] * b_in[e] + b_ih[r] + b_hh[r]
// gate rows r: 0-7 = i, 8-15 = f, 16-23 = g, 24-31 = o (PyTorch order)
// ---------------------------------------------------------------------------
__global__ void prep_kernel(
    const float* __restrict__ W_in, const float* __restrict__ b_in,
    const float* __restrict__ Wih0, const float* __restrict__ Whh0,
    const float* __restrict__ bih0, const float* __restrict__ bhh0,
    const float* __restrict__ Wih1, const float* __restrict__ Whh1,
    const float* __restrict__ bih1, const float* __restrict__ bhh1)
{
    int k = threadIdx.x;
    if (k >= 64) return;
    int ph = k >> 5, r = k & 31;
    const float* Wih = ph ? Wih1 : Wih0;
    const float* Whh = ph ? Whh1 : Whh0;
    const float* bih = ph ? bih1 : bih0;
    const float* bhh = ph ? bhh1 : bhh0;

    float wx0 = 0.f, wx1 = 0.f, bb = bih[r] + bhh[r];
    for (int e = 0; e < 16; e++) {
        float w = Wih[r * 16 + e];
        wx0 += w * W_in[e * 2 + 0];
        wx1 += w * W_in[e * 2 + 1];
        bb  += w * b_in[e];
    }
    int g = r >> 3, j = r & 7;
    ull* dst = g_wp + ((size_t)((ph * 8 + j) * 4 + g)) * 12;
    dst[0] = pack2(wx0, wx0);
    dst[1] = pack2(wx1, wx1);
    for (int q = 0; q < 8; q++) {
        float w = Whh[r * 8 + q];
        dst[2 + q] = pack2(w, w);
    }
    dst[10] = pack2(bb, bb);
    dst[11] = 0ull;
}

// ---------------------------------------------------------------------------
// main LSTM kernel: each thread owns 2 batch elements (1 f32x2 pair).
// Time loop is NOT unrolled (prevents cross-step weight-load hoisting that
// blew registers to 255 and caused state spills in R3).
// ---------------------------------------------------------------------------
__device__ __forceinline__ void lstm_steps(
    const float* __restrict__ x, int T, const ull* __restrict__ swp,
    int e0, ull h[8], ull c[8])
{
#pragma unroll 1
    for (int s = 0; s < T; s++) {
        // [T,B,2] layout: 16B covers both owned elements, fully coalesced
        float4 xv = *(const float4*)(x + ((size_t)s * BATCH + e0) * 2);
        ull x0 = pack2(xv.x, xv.z);
        ull x1 = pack2(xv.y, xv.w);

        ull hn[8];
#pragma unroll
        for (int j = 0; j < 8; j++) {
            const ull* wj = swp + j * 48;
            ull acc[4];
#pragma unroll
            for (int g = 0; g < 4; g++) {
                const ull* w = wj + g * 12;
                ull a = fma2(w[0], x0, w[10]);
                a = fma2(w[1], x1, a);
#pragma unroll
                for (int q = 0; q < 8; q++)
                    a = fma2(w[2 + q], h[q], a);
                acc[g] = a;
            }
            float gi0, gi1, gf0, gf1, gg0, gg1, go0, go1, cl0, cl1;
            unpack2(acc[0], gi0, gi1);
            unpack2(acc[1], gf0, gf1);
            unpack2(acc[2], gg0, gg1);
            unpack2(acc[3], go0, go1);
            unpack2(c[j], cl0, cl1);
            float cn0 = fmaf(sig_f(gf0), cl0, sig_f(gi0) * tanh_hw(gg0));
            float cn1 = fmaf(sig_f(gf1), cl1, sig_f(gi1) * tanh_hw(gg1));
            float hn0 = sig_f(go0) * tanh_hw(cn0);
            float hn1 = sig_f(go1) * tanh_hw(cn1);
            c[j]  = pack2(cn0, cn1);
            hn[j] = pack2(hn0, hn1);
        }
#pragma unroll
        for (int j = 0; j < 8; j++) h[j] = hn[j];
    }
}

__device__ __forceinline__ void load_state8(const float* __restrict__ src, int e0, ull v[8]) {
    float4 a0 = *(const float4*)(src + (size_t)e0 * 8);
    float4 a1 = *(const float4*)(src + (size_t)e0 * 8 + 4);
    float4 b0 = *(const float4*)(src + (size_t)(e0 + 1) * 8);
    float4 b1 = *(const float4*)(src + (size_t)(e0 + 1) * 8 + 4);
    v[0] = pack2(a0.x, b0.x); v[1] = pack2(a0.y, b0.y);
    v[2] = pack2(a0.z, b0.z); v[3] = pack2(a0.w, b0.w);
    v[4] = pack2(a1.x, b1.x); v[5] = pack2(a1.y, b1.y);
    v[6] = pack2(a1.z, b1.z); v[7] = pack2(a1.w, b1.w);
}

// output is h stored unit-major: out[u*BATCH + e] = h[e][u]
__device__ __forceinline__ void store_h(float* __restrict__ out, int e0, ull h[8]) {
#pragma unroll
    for (int u = 0; u < 8; u++) {
        float a, b;
        unpack2(h[u], a, b);
        *(float2*)(out + (size_t)u * BATCH + e0) = make_float2(a, b);
    }
}

__global__ void __launch_bounds__(NTHREADS, 3) lstm_kernel(
    const float* __restrict__ obs, const float* __restrict__ pre,
    const float* __restrict__ h0, const float* __restrict__ c0,
    const float* __restrict__ c0p, float* __restrict__ out)
{
    __shared__ ull sw[2 * 8 * 4 * 12];
    for (int i = threadIdx.x; i < 2 * 8 * 4 * 12; i += NTHREADS) sw[i] = g_wp[i];
    __syncthreads();

    const int tid = blockIdx.x * NTHREADS + threadIdx.x;
    const int e0 = tid * M_ELEMS;

    ull h[8], c[8];
    load_state8(h0, e0, h);
    load_state8(c0, e0, c);

    // phase 1: obs LSTM
    lstm_steps(obs, T_OBS, sw, e0, h, c);
    store_h(out, e0, h);                      // c_out = h_obs, unit-major

    // phase 2: pre LSTM — h carries over, cell state re-initialized
    load_state8(c0p, e0, c);
    lstm_steps(pre, T_PRE, sw + 8 * 4 * 12, e0, h, c);
    store_h(out + (size_t)BATCH * HID, e0, h); // x_out = h_pre, unit-major
}

extern "C" void kernel_launch(void* const* d_in, const int* in_sizes, int n_in,
                              void* d_out, int out_size) {
    const float* obs  = (const float*)d_in[0];
    const float* pre  = (const float*)d_in[1];
    const float* h0   = (const float*)d_in[2];
    const float* c0   = (const float*)d_in[3];
    const float* c0p  = (const float*)d_in[4];
    const float* W_in = (const float*)d_in[5];
    const float* b_in = (const float*)d_in[6];
    const float* Wih0 = (const float*)d_in[7];
    const float* Whh0 = (const float*)d_in[8];
    const float* bih0 = (const float*)d_in[9];
    const float* bhh0 = (const float*)d_in[10];
    const float* Wih1 = (const float*)d_in[11];
    const float* Whh1 = (const float*)d_in[12];
    const float* bih1 = (const float*)d_in[13];
    const float* bhh1 = (const float*)d_in[14];
    float* out = (float*)d_out;

    prep_kernel<<<1, 64>>>(W_in, b_in, Wih0, Whh0, bih0, bhh0,
                           Wih1, Whh1, bih1, bhh1);
    lstm_kernel<<<NBLOCKS, NTHREADS>>>(obs, pre, h0, c0, c0p, out);
}

// round 5
// speedup vs baseline: 6.4807x; 6.4807x over previous
#include <cuda_runtime.h>

typedef unsigned long long ull;

#define T_OBS 8
#define T_PRE 12
#define BATCH 524288
#define HID 8
#define NTHREADS 128
#define M_ELEMS 2                                   // elements per thread = 1 f32x2 pair
#define NBLOCKS (BATCH / M_ELEMS / NTHREADS)        // 2048

// packed duplicated weights: [phase][unit j][gate g][12] with
// slot 0..1 = wx (combined input weights), 2..9 = whh, 10 = combined bias, 11 = pad
__device__ ull g_wp[2 * 8 * 4 * 12];

__device__ __forceinline__ ull pack2(float lo, float hi) {
    ull r; asm("mov.b64 %0, {%1, %2};" : "=l"(r) : "f"(lo), "f"(hi)); return r;
}
__device__ __forceinline__ void unpack2(ull v, float &lo, float &hi) {
    asm("mov.b64 {%0, %1}, %2;" : "=f"(lo), "=f"(hi) : "l"(v));
}
__device__ __forceinline__ ull fma2(ull a, ull b, ull c) {
    ull d; asm("fma.rn.f32x2 %0, %1, %2, %3;" : "=l"(d) : "l"(a), "l"(b), "l"(c)); return d;
}
// HW tanh: 1 MUFU op, max abs err ~2^-10.7 (validated rel_err 5e-6 in R4)
__device__ __forceinline__ float tanh_hw(float x) {
    float y; asm("tanh.approx.f32 %0, %1;" : "=f"(y) : "f"(x)); return y;
}
// sigmoid(x) = 0.5 + 0.5*tanh(x/2) : MUL, MUFU, FMA
__device__ __forceinline__ float sig_f(float x) {
    return fmaf(tanh_hw(0.5f * x), 0.5f, 0.5f);
}

// ---------------------------------------------------------------------------
// prep: fold embedding into gate matrices; duplicate-pack everything for f32x2
// gate rows r: 0-7 = i, 8-15 = f, 16-23 = g, 24-31 = o (PyTorch order)
// ---------------------------------------------------------------------------
__global__ void prep_kernel(
    const float* __restrict__ W_in, const float* __restrict__ b_in,
    const float* __restrict__ Wih0, const float* __restrict__ Whh0,
    const float* __restrict__ bih0, const float* __restrict__ bhh0,
    const float* __restrict__ Wih1, const float* __restrict__ Whh1,
    const float* __restrict__ bih1, const float* __restrict__ bhh1)
{
    int k = threadIdx.x;
    if (k >= 64) return;
    int ph = k >> 5, r = k & 31;
    const float* Wih = ph ? Wih1 : Wih0;
    const float* Whh = ph ? Whh1 : Whh0;
    const float* bih = ph ? bih1 : bih0;
    const float* bhh = ph ? bhh1 : bhh0;

    float wx0 = 0.f, wx1 = 0.f, bb = bih[r] + bhh[r];
    for (int e = 0; e < 16; e++) {
        float w = Wih[r * 16 + e];
        wx0 += w * W_in[e * 2 + 0];
        wx1 += w * W_in[e * 2 + 1];
        bb  += w * b_in[e];
    }
    int g = r >> 3, j = r & 7;
    ull* dst = g_wp + ((size_t)((ph * 8 + j) * 4 + g)) * 12;
    dst[0] = pack2(wx0, wx0);
    dst[1] = pack2(wx1, wx1);
    for (int q = 0; q < 8; q++) {
        float w = Whh[r * 8 + q];
        dst[2 + q] = pack2(w, w);
    }
    dst[10] = pack2(bb, bb);
    dst[11] = 0ull;
}

// ---------------------------------------------------------------------------
// main LSTM kernel: each thread owns 2 batch elements (1 f32x2 pair).
// BOTH the time loop AND the unit (j) loop are serialized: the unrolled
// j-loop let ptxas hoist 8x12 weight LDS into registers (the R3/R4 spill
// bomb). Serial j keeps the working set ~110 regs -> fits 128-reg cap.
// ---------------------------------------------------------------------------
__device__ __forceinline__ void lstm_steps(
    const float* __restrict__ x, int T, const ull* __restrict__ swp,
    int e0, ull h[8], ull c[8])
{
#pragma unroll 1
    for (int s = 0; s < T; s++) {
        // [T,B,2] layout: 16B covers both owned elements, fully coalesced
        float4 xv = *(const float4*)(x + ((size_t)s * BATCH + e0) * 2);
        ull x0 = pack2(xv.x, xv.z);
        ull x1 = pack2(xv.y, xv.w);

        ull hn[8];
#pragma unroll 1
        for (int j = 0; j < 8; j++) {
            const ull* wj = swp + j * 48;
            ull acc[4];
#pragma unroll
            for (int g = 0; g < 4; g++) {
                const ull* w = wj + g * 12;
                ull a = fma2(w[0], x0, w[10]);
                a = fma2(w[1], x1, a);
#pragma unroll
                for (int q = 0; q < 8; q++)
                    a = fma2(w[2 + q], h[q], a);
                acc[g] = a;
            }
            float gi0, gi1, gf0, gf1, gg0, gg1, go0, go1, cl0, cl1;
            unpack2(acc[0], gi0, gi1);
            unpack2(acc[1], gf0, gf1);
            unpack2(acc[2], gg0, gg1);
            unpack2(acc[3], go0, go1);
            unpack2(c[j], cl0, cl1);
            float cn0 = fmaf(sig_f(gf0), cl0, sig_f(gi0) * tanh_hw(gg0));
            float cn1 = fmaf(sig_f(gf1), cl1, sig_f(gi1) * tanh_hw(gg1));
            float hn0 = sig_f(go0) * tanh_hw(cn0);
            float hn1 = sig_f(go1) * tanh_hw(cn1);
            c[j]  = pack2(cn0, cn1);
            hn[j] = pack2(hn0, hn1);
        }
#pragma unroll
        for (int j = 0; j < 8; j++) h[j] = hn[j];
    }
}

__device__ __forceinline__ void load_state8(const float* __restrict__ src, int e0, ull v[8]) {
    float4 a0 = *(const float4*)(src + (size_t)e0 * 8);
    float4 a1 = *(const float4*)(src + (size_t)e0 * 8 + 4);
    float4 b0 = *(const float4*)(src + (size_t)(e0 + 1) * 8);
    float4 b1 = *(const float4*)(src + (size_t)(e0 + 1) * 8 + 4);
    v[0] = pack2(a0.x, b0.x); v[1] = pack2(a0.y, b0.y);
    v[2] = pack2(a0.z, b0.z); v[3] = pack2(a0.w, b0.w);
    v[4] = pack2(a1.x, b1.x); v[5] = pack2(a1.y, b1.y);
    v[6] = pack2(a1.z, b1.z); v[7] = pack2(a1.w, b1.w);
}

// output is h stored unit-major: out[u*BATCH + e] = h[e][u]
__device__ __forceinline__ void store_h(float* __restrict__ out, int e0, ull h[8]) {
#pragma unroll
    for (int u = 0; u < 8; u++) {
        float a, b;
        unpack2(h[u], a, b);
        *(float2*)(out + (size_t)u * BATCH + e0) = make_float2(a, b);
    }
}

__global__ void __launch_bounds__(NTHREADS, 4) lstm_kernel(
    const float* __restrict__ obs, const float* __restrict__ pre,
    const float* __restrict__ h0, const float* __restrict__ c0,
    const float* __restrict__ c0p, float* __restrict__ out)
{
    __shared__ ull sw[2 * 8 * 4 * 12];
    for (int i = threadIdx.x; i < 2 * 8 * 4 * 12; i += NTHREADS) sw[i] = g_wp[i];
    __syncthreads();

    const int tid = blockIdx.x * NTHREADS + threadIdx.x;
    const int e0 = tid * M_ELEMS;

    ull h[8], c[8];
    load_state8(h0, e0, h);
    load_state8(c0, e0, c);

    // phase 1: obs LSTM
    lstm_steps(obs, T_OBS, sw, e0, h, c);
    store_h(out, e0, h);                      // c_out = h_obs, unit-major

    // phase 2: pre LSTM — h carries over, cell state re-initialized
    load_state8(c0p, e0, c);
    lstm_steps(pre, T_PRE, sw + 8 * 4 * 12, e0, h, c);
    store_h(out + (size_t)BATCH * HID, e0, h); // x_out = h_pre, unit-major
}

extern "C" void kernel_launch(void* const* d_in, const int* in_sizes, int n_in,
                              void* d_out, int out_size) {
    const float* obs  = (const float*)d_in[0];
    const float* pre  = (const float*)d_in[1];
    const float* h0   = (const float*)d_in[2];
    const float* c0   = (const float*)d_in[3];
    const float* c0p  = (const float*)d_in[4];
    const float* W_in = (const float*)d_in[5];
    const float* b_in = (const float*)d_in[6];
    const float* Wih0 = (const float*)d_in[7];
    const float* Whh0 = (const float*)d_in[8];
    const float* bih0 = (const float*)d_in[9];
    const float* bhh0 = (const float*)d_in[10];
    const float* Wih1 = (const float*)d_in[11];
    const float* Whh1 = (const float*)d_in[12];
    const float* bih1 = (const float*)d_in[13];
    const float* bhh1 = (const float*)d_in[14];
    float* out = (float*)d_out;

    prep_kernel<<<1, 64>>>(W_in, b_in, Wih0, Whh0, bih0, bhh0,
                           Wih1, Whh1, bih1, bhh1);
    lstm_kernel<<<NBLOCKS, NTHREADS>>>(obs, pre, h0, c0, c0p, out);
}

// round 6
// speedup vs baseline: 6.5336x; 1.0082x over previous
#include <cuda_runtime.h>

typedef unsigned long long ull;

#define T_OBS 8
#define T_PRE 12
#define BATCH 524288
#define HID 8
#define NTHREADS 128
#define M_ELEMS 2                                   // elements per thread = 1 f32x2 pair
#define NBLOCKS (BATCH / M_ELEMS / NTHREADS)        // 2048

// packed duplicated weights: [phase][unit j][gate g][12 ull] laid out as six
// 16B slots for LDS.128: [wx0,wx1][wh0,wh1][wh2,wh3][wh4,wh5][wh6,wh7][bias,pad]
// i/f/o gate rows are pre-scaled by 0.5 (sigmoid folding).
__device__ __align__(16) ull g_wp[2 * 8 * 4 * 12];

__device__ __forceinline__ ull pack2(float lo, float hi) {
    ull r; asm("mov.b64 %0, {%1, %2};" : "=l"(r) : "f"(lo), "f"(hi)); return r;
}
__device__ __forceinline__ void unpack2(ull v, float &lo, float &hi) {
    asm("mov.b64 {%0, %1}, %2;" : "=f"(lo), "=f"(hi) : "l"(v));
}
__device__ __forceinline__ ull fma2(ull a, ull b, ull c) {
    ull d; asm("fma.rn.f32x2 %0, %1, %2, %3;" : "=l"(d) : "l"(a), "l"(b), "l"(c)); return d;
}
// HW tanh: 1 MUFU op (validated rel_err 5e-6)
__device__ __forceinline__ float tanh_hw(float x) {
    float y; asm("tanh.approx.f32 %0, %1;" : "=f"(y) : "f"(x)); return y;
}
// sigmoid with the 0.5x pre-scale folded into the weights:
// sig(2*acc) where acc = 0.5*gate_preact  ->  fma(tanh(acc), 0.5, 0.5)
__device__ __forceinline__ float sig_pre(float acc) {
    return fmaf(tanh_hw(acc), 0.5f, 0.5f);
}

// ---------------------------------------------------------------------------
// prep: fold embedding into gate matrices; duplicate-pack for f32x2;
// pre-scale i/f/o rows by 0.5 (sigmoid folding).
// gate rows r: 0-7 = i, 8-15 = f, 16-23 = g, 24-31 = o (PyTorch order)
// ---------------------------------------------------------------------------
__global__ void prep_kernel(
    const float* __restrict__ W_in, const float* __restrict__ b_in,
    const float* __restrict__ Wih0, const float* __restrict__ Whh0,
    const float* __restrict__ bih0, const float* __restrict__ bhh0,
    const float* __restrict__ Wih1, const float* __restrict__ Whh1,
    const float* __restrict__ bih1, const float* __restrict__ bhh1)
{
    int k = threadIdx.x;
    if (k >= 64) return;
    int ph = k >> 5, r = k & 31;
    const float* Wih = ph ? Wih1 : Wih0;
    const float* Whh = ph ? Whh1 : Whh0;
    const float* bih = ph ? bih1 : bih0;
    const float* bhh = ph ? bhh1 : bhh0;

    float wx0 = 0.f, wx1 = 0.f, bb = bih[r] + bhh[r];
    for (int e = 0; e < 16; e++) {
        float w = Wih[r * 16 + e];
        wx0 += w * W_in[e * 2 + 0];
        wx1 += w * W_in[e * 2 + 1];
        bb  += w * b_in[e];
    }
    int g = r >> 3, j = r & 7;
    float sc = (g == 2) ? 1.0f : 0.5f;   // fold sigmoid 0.5x into i/f/o rows
    wx0 *= sc; wx1 *= sc; bb *= sc;

    ull* dst = g_wp + ((size_t)((ph * 8 + j) * 4 + g)) * 12;
    dst[0] = pack2(wx0, wx0);            // slot0: wx0, wx1
    dst[1] = pack2(wx1, wx1);
    for (int q = 0; q < 8; q++) {        // slots1-4: whh pairs
        float w = Whh[r * 8 + q] * sc;
        dst[2 + q] = pack2(w, w);
    }
    dst[10] = pack2(bb, bb);             // slot5: bias, pad
    dst[11] = 0ull;
}

// ---------------------------------------------------------------------------
// main LSTM kernel: each thread owns 2 batch elements (1 f32x2 pair).
// Time and unit loops serialized (register discipline, R5 lesson).
// Weights loaded as 16B LDS.128 (halves shared-pipe issue, the R5 binder).
// ---------------------------------------------------------------------------
__device__ __forceinline__ void lstm_steps(
    const float* __restrict__ x, int T, const ull* __restrict__ swp,
    int e0, ull h[8], ull c[8])
{
#pragma unroll 1
    for (int s = 0; s < T; s++) {
        // [T,B,2] layout: 16B covers both owned elements, fully coalesced
        float4 xv = *(const float4*)(x + ((size_t)s * BATCH + e0) * 2);
        ull x0 = pack2(xv.x, xv.z);
        ull x1 = pack2(xv.y, xv.w);

        ull hn[8];
#pragma unroll 1
        for (int j = 0; j < 8; j++) {
            const ulonglong2* wj = (const ulonglong2*)(swp + j * 48);
            ull acc[4];
#pragma unroll
            for (int g = 0; g < 4; g++) {
                const ulonglong2* w = wj + g * 6;
                ulonglong2 p0 = w[0];               // wx0, wx1
                ulonglong2 p5 = w[5];               // bias, pad
                ull a = fma2(p0.x, x0, p5.x);
                a = fma2(p0.y, x1, a);
                ulonglong2 p1 = w[1], p2 = w[2], p3 = w[3], p4 = w[4];
                a = fma2(p1.x, h[0], a);
                a = fma2(p1.y, h[1], a);
                a = fma2(p2.x, h[2], a);
                a = fma2(p2.y, h[3], a);
                a = fma2(p3.x, h[4], a);
                a = fma2(p3.y, h[5], a);
                a = fma2(p4.x, h[6], a);
                a = fma2(p4.y, h[7], a);
                acc[g] = a;
            }
            float gi0, gi1, gf0, gf1, gg0, gg1, go0, go1, cl0, cl1;
            unpack2(acc[0], gi0, gi1);
            unpack2(acc[1], gf0, gf1);
            unpack2(acc[2], gg0, gg1);
            unpack2(acc[3], go0, go1);
            unpack2(c[j], cl0, cl1);
            float cn0 = fmaf(sig_pre(gf0), cl0, sig_pre(gi0) * tanh_hw(gg0));
            float cn1 = fmaf(sig_pre(gf1), cl1, sig_pre(gi1) * tanh_hw(gg1));
            float hn0 = sig_pre(go0) * tanh_hw(cn0);
            float hn1 = sig_pre(go1) * tanh_hw(cn1);
            c[j]  = pack2(cn0, cn1);
            hn[j] = pack2(hn0, hn1);
        }
#pragma unroll
        for (int j = 0; j < 8; j++) h[j] = hn[j];
    }
}

__device__ __forceinline__ void load_state8(const float* __restrict__ src, int e0, ull v[8]) {
    float4 a0 = *(const float4*)(src + (size_t)e0 * 8);
    float4 a1 = *(const float4*)(src + (size_t)e0 * 8 + 4);
    float4 b0 = *(const float4*)(src + (size_t)(e0 + 1) * 8);
    float4 b1 = *(const float4*)(src + (size_t)(e0 + 1) * 8 + 4);
    v[0] = pack2(a0.x, b0.x); v[1] = pack2(a0.y, b0.y);
    v[2] = pack2(a0.z, b0.z); v[3] = pack2(a0.w, b0.w);
    v[4] = pack2(a1.x, b1.x); v[5] = pack2(a1.y, b1.y);
    v[6] = pack2(a1.z, b1.z); v[7] = pack2(a1.w, b1.w);
}

// output is h stored unit-major: out[u*BATCH + e] = h[e][u]
__device__ __forceinline__ void store_h(float* __restrict__ out, int e0, ull h[8]) {
#pragma unroll
    for (int u = 0; u < 8; u++) {
        float a, b;
        unpack2(h[u], a, b);
        *(float2*)(out + (size_t)u * BATCH + e0) = make_float2(a, b);
    }
}

__global__ void __launch_bounds__(NTHREADS, 4) lstm_kernel(
    const float* __restrict__ obs, const float* __restrict__ pre,
    const float* __restrict__ h0, const float* __restrict__ c0,
    const float* __restrict__ c0p, float* __restrict__ out)
{
    __shared__ __align__(16) ull sw[2 * 8 * 4 * 12];
    for (int i = threadIdx.x; i < 2 * 8 * 4 * 12; i += NTHREADS) sw[i] = g_wp[i];
    __syncthreads();

    const int tid = blockIdx.x * NTHREADS + threadIdx.x;
    const int e0 = tid * M_ELEMS;

    ull h[8], c[8];
    load_state8(h0, e0, h);
    load_state8(c0, e0, c);

    // phase 1: obs LSTM
    lstm_steps(obs, T_OBS, sw, e0, h, c);
    store_h(out, e0, h);                      // c_out = h_obs, unit-major

    // phase 2: pre LSTM — h carries over, cell state re-initialized
    load_state8(c0p, e0, c);
    lstm_steps(pre, T_PRE, sw + 8 * 4 * 12, e0, h, c);
    store_h(out + (size_t)BATCH * HID, e0, h); // x_out = h_pre, unit-major
}

extern "C" void kernel_launch(void* const* d_in, const int* in_sizes, int n_in,
                              void* d_out, int out_size) {
    const float* obs  = (const float*)d_in[0];
    const float* pre  = (const float*)d_in[1];
    const float* h0   = (const float*)d_in[2];
    const float* c0   = (const float*)d_in[3];
    const float* c0p  = (const float*)d_in[4];
    const float* W_in = (const float*)d_in[5];
    const float* b_in = (const float*)d_in[6];
    const float* Wih0 = (const float*)d_in[7];
    const float* Whh0 = (const float*)d_in[8];
    const float* bih0 = (const float*)d_in[9];
    const float* bhh0 = (const float*)d_in[10];
    const float* Wih1 = (const float*)d_in[11];
    const float* Whh1 = (const float*)d_in[12];
    const float* bih1 = (const float*)d_in[13];
    const float* bhh1 = (const float*)d_in[14];
    float* out = (float*)d_out;

    prep_kernel<<<1, 64>>>(W_in, b_in, Wih0, Whh0, bih0, bhh0,
                           Wih1, Whh1, bih1, bhh1);
    lstm_kernel<<<NBLOCKS, NTHREADS>>>(obs, pre, h0, c0, c0p, out);
}

// round 7
// speedup vs baseline: 7.9566x; 1.2178x over previous
#include <cuda_runtime.h>

typedef unsigned long long ull;

#define T_OBS 8
#define T_PRE 12
#define BATCH 524288
#define HID 8
#define NTHREADS 128
#define M_ELEMS 4                                   // elements per thread = 2 f32x2 pairs
#define NBLOCKS (BATCH / M_ELEMS / NTHREADS)        // 1024

// packed duplicated weights: [phase][unit j][gate g][12 ull] laid out as six
// 16B slots for LDS.128: [wx0,wx1][wh0,wh1][wh2,wh3][wh4,wh5][wh6,wh7][bias,pad]
// i/f/o gate rows are pre-scaled by 0.5 (sigmoid folding).
__device__ __align__(16) ull g_wp[2 * 8 * 4 * 12];

__device__ __forceinline__ ull pack2(float lo, float hi) {
    ull r; asm("mov.b64 %0, {%1, %2};" : "=l"(r) : "f"(lo), "f"(hi)); return r;
}
__device__ __forceinline__ void unpack2(ull v, float &lo, float &hi) {
    asm("mov.b64 {%0, %1}, %2;" : "=f"(lo), "=f"(hi) : "l"(v));
}
__device__ __forceinline__ ull fma2(ull a, ull b, ull c) {
    ull d; asm("fma.rn.f32x2 %0, %1, %2, %3;" : "=l"(d) : "l"(a), "l"(b), "l"(c)); return d;
}
// HW tanh: 1 MUFU op (validated rel_err 5e-6)
__device__ __forceinline__ float tanh_hw(float x) {
    float y; asm("tanh.approx.f32 %0, %1;" : "=f"(y) : "f"(x)); return y;
}
// sigmoid with the 0.5x pre-scale folded into the weights
__device__ __forceinline__ float sig_pre(float acc) {
    return fmaf(tanh_hw(acc), 0.5f, 0.5f);
}

// ---------------------------------------------------------------------------
// prep: fold embedding into gate matrices; duplicate-pack for f32x2;
// pre-scale i/f/o rows by 0.5 (sigmoid folding).
// gate rows r: 0-7 = i, 8-15 = f, 16-23 = g, 24-31 = o (PyTorch order)
// ---------------------------------------------------------------------------
__global__ void prep_kernel(
    const float* __restrict__ W_in, const float* __restrict__ b_in,
    const float* __restrict__ Wih0, const float* __restrict__ Whh0,
    const float* __restrict__ bih0, const float* __restrict__ bhh0,
    const float* __restrict__ Wih1, const float* __restrict__ Whh1,
    const float* __restrict__ bih1, const float* __restrict__ bhh1)
{
    int k = threadIdx.x;
    if (k >= 64) return;
    int ph = k >> 5, r = k & 31;
    const float* Wih = ph ? Wih1 : Wih0;
    const float* Whh = ph ? Whh1 : Whh0;
    const float* bih = ph ? bih1 : bih0;
    const float* bhh = ph ? bhh1 : bhh0;

    float wx0 = 0.f, wx1 = 0.f, bb = bih[r] + bhh[r];
    for (int e = 0; e < 16; e++) {
        float w = Wih[r * 16 + e];
        wx0 += w * W_in[e * 2 + 0];
        wx1 += w * W_in[e * 2 + 1];
        bb  += w * b_in[e];
    }
    int g = r >> 3, j = r & 7;
    float sc = (g == 2) ? 1.0f : 0.5f;   // fold sigmoid 0.5x into i/f/o rows
    wx0 *= sc; wx1 *= sc; bb *= sc;

    ull* dst = g_wp + ((size_t)((ph * 8 + j) * 4 + g)) * 12;
    dst[0] = pack2(wx0, wx0);            // slot0: wx0, wx1
    dst[1] = pack2(wx1, wx1);
    for (int q = 0; q < 8; q++) {        // slots1-4: whh pairs
        float w = Whh[r * 8 + q] * sc;
        dst[2 + q] = pack2(w, w);
    }
    dst[10] = pack2(bb, bb);             // slot5: bias, pad
    dst[11] = 0ull;
}

// ---------------------------------------------------------------------------
// main LSTM kernel: each thread owns 4 batch elements (2 f32x2 pairs) so each
// broadcast weight read is amortized over 2x the elements (L1 wavefronts were
// the R6 binder). Time and unit loops stay serialized (register discipline).
// ---------------------------------------------------------------------------
__device__ __forceinline__ void lstm_steps(
    const float* __restrict__ x, int T, const ull* __restrict__ swp,
    int e0, ull h[2][8], ull c[2][8])
{
#pragma unroll 1
    for (int s = 0; s < T; s++) {
        ull x0[2], x1[2];
#pragma unroll
        for (int p = 0; p < 2; p++) {
            // [T,B,2] layout: 16B per pair of elements, fully coalesced
            float4 xv = *(const float4*)(x + ((size_t)s * BATCH + (e0 + 2 * p)) * 2);
            x0[p] = pack2(xv.x, xv.z);
            x1[p] = pack2(xv.y, xv.w);
        }
        ull hn[2][8];
#pragma unroll 1
        for (int j = 0; j < 8; j++) {
            const ulonglong2* wj = (const ulonglong2*)(swp + j * 48);
            ull acc[4][2];
#pragma unroll
            for (int g = 0; g < 4; g++) {
                const ulonglong2* w = wj + g * 6;
                ulonglong2 p0 = w[0];               // wx0, wx1
                ulonglong2 p1 = w[1], p2 = w[2], p3 = w[3], p4 = w[4];
                ulonglong2 p5 = w[5];               // bias, pad
#pragma unroll
                for (int p = 0; p < 2; p++) {
                    ull a = fma2(p0.x, x0[p], p5.x);
                    a = fma2(p0.y, x1[p], a);
                    a = fma2(p1.x, h[p][0], a);
                    a = fma2(p1.y, h[p][1], a);
                    a = fma2(p2.x, h[p][2], a);
                    a = fma2(p2.y, h[p][3], a);
                    a = fma2(p3.x, h[p][4], a);
                    a = fma2(p3.y, h[p][5], a);
                    a = fma2(p4.x, h[p][6], a);
                    a = fma2(p4.y, h[p][7], a);
                    acc[g][p] = a;
                }
            }
#pragma unroll
            for (int p = 0; p < 2; p++) {
                float gi0, gi1, gf0, gf1, gg0, gg1, go0, go1, cl0, cl1;
                unpack2(acc[0][p], gi0, gi1);
                unpack2(acc[1][p], gf0, gf1);
                unpack2(acc[2][p], gg0, gg1);
                unpack2(acc[3][p], go0, go1);
                unpack2(c[p][j], cl0, cl1);
                float cn0 = fmaf(sig_pre(gf0), cl0, sig_pre(gi0) * tanh_hw(gg0));
                float cn1 = fmaf(sig_pre(gf1), cl1, sig_pre(gi1) * tanh_hw(gg1));
                float hn0 = sig_pre(go0) * tanh_hw(cn0);
                float hn1 = sig_pre(go1) * tanh_hw(cn1);
                c[p][j]  = pack2(cn0, cn1);
                hn[p][j] = pack2(hn0, hn1);
            }
        }
#pragma unroll
        for (int j = 0; j < 8; j++) { h[0][j] = hn[0][j]; h[1][j] = hn[1][j]; }
    }
}

__device__ __forceinline__ void load_state8(const float* __restrict__ src, int e0, ull v[2][8]) {
#pragma unroll
    for (int p = 0; p < 2; p++) {
        int ea = e0 + 2 * p;
        float4 a0 = *(const float4*)(src + (size_t)ea * 8);
        float4 a1 = *(const float4*)(src + (size_t)ea * 8 + 4);
        float4 b0 = *(const float4*)(src + (size_t)(ea + 1) * 8);
        float4 b1 = *(const float4*)(src + (size_t)(ea + 1) * 8 + 4);
        v[p][0] = pack2(a0.x, b0.x); v[p][1] = pack2(a0.y, b0.y);
        v[p][2] = pack2(a0.z, b0.z); v[p][3] = pack2(a0.w, b0.w);
        v[p][4] = pack2(a1.x, b1.x); v[p][5] = pack2(a1.y, b1.y);
        v[p][6] = pack2(a1.z, b1.z); v[p][7] = pack2(a1.w, b1.w);
    }
}

// output is h stored unit-major: out[u*BATCH + e] = h[e][u]
__device__ __forceinline__ void store_h(float* __restrict__ out, int e0, ull h[2][8]) {
#pragma unroll
    for (int u = 0; u < 8; u++) {
        float a, b, cc, d;
        unpack2(h[0][u], a, b);
        unpack2(h[1][u], cc, d);
        *(float4*)(out + (size_t)u * BATCH + e0) = make_float4(a, b, cc, d);
    }
}

__global__ void __launch_bounds__(NTHREADS, 3) lstm_kernel(
    const float* __restrict__ obs, const float* __restrict__ pre,
    const float* __restrict__ h0, const float* __restrict__ c0,
    const float* __restrict__ c0p, float* __restrict__ out)
{
    __shared__ __align__(16) ull sw[2 * 8 * 4 * 12];
    for (int i = threadIdx.x; i < 2 * 8 * 4 * 12; i += NTHREADS) sw[i] = g_wp[i];
    __syncthreads();

    const int tid = blockIdx.x * NTHREADS + threadIdx.x;
    const int e0 = tid * M_ELEMS;

    ull h[2][8], c[2][8];
    load_state8(h0, e0, h);
    load_state8(c0, e0, c);

    // phase 1: obs LSTM
    lstm_steps(obs, T_OBS, sw, e0, h, c);
    store_h(out, e0, h);                      // c_out = h_obs, unit-major

    // phase 2: pre LSTM — h carries over, cell state re-initialized
    load_state8(c0p, e0, c);
    lstm_steps(pre, T_PRE, sw + 8 * 4 * 12, e0, h, c);
    store_h(out + (size_t)BATCH * HID, e0, h); // x_out = h_pre, unit-major
}

extern "C" void kernel_launch(void* const* d_in, const int* in_sizes, int n_in,
                              void* d_out, int out_size) {
    const float* obs  = (const float*)d_in[0];
    const float* pre  = (const float*)d_in[1];
    const float* h0   = (const float*)d_in[2];
    const float* c0   = (const float*)d_in[3];
    const float* c0p  = (const float*)d_in[4];
    const float* W_in = (const float*)d_in[5];
    const float* b_in = (const float*)d_in[6];
    const float* Wih0 = (const float*)d_in[7];
    const float* Whh0 = (const float*)d_in[8];
    const float* bih0 = (const float*)d_in[9];
    const float* bhh0 = (const float*)d_in[10];
    const float* Wih1 = (const float*)d_in[11];
    const float* Whh1 = (const float*)d_in[12];
    const float* bih1 = (const float*)d_in[13];
    const float* bhh1 = (const float*)d_in[14];
    float* out = (float*)d_out;

    prep_kernel<<<1, 64>>>(W_in, b_in, Wih0, Whh0, bih0, bhh0,
                           Wih1, Whh1, bih1, bhh1);
    lstm_kernel<<<NBLOCKS, NTHREADS>>>(obs, pre, h0, c0, c0p, out);
}